// round 1
// baseline (speedup 1.0000x reference)
#include <cuda_runtime.h>
#include <cstdint>
#include <float.h>

#define BB 16
#define NN 2048
#define CC 80

// ---------------- scratch (device globals; no allocations) ----------------
__device__ float4        g_xyxy[BB * NN];
__device__ float         g_key [BB * NN];
__device__ float         g_obj [BB * NN];
__device__ float         g_conf[BB * NN];
__device__ int           g_cls [BB * NN];

__device__ float4        g_xyxy_s[BB * NN];
__device__ float         g_obj_s [BB * NN];
__device__ float         g_conf_s[BB * NN];
__device__ unsigned char g_cls_s [BB * NN];
__device__ int           g_M[BB];

// ---------------- kernel 1: per-element prep (one warp per element) -------
__global__ void prep_kernel(const float* __restrict__ boxes,
                            const float* __restrict__ objn,
                            const float* __restrict__ logits,
                            float* __restrict__ out)
{
    int gw   = (blockIdx.x * blockDim.x + threadIdx.x) >> 5;   // element index
    int lane = threadIdx.x & 31;
    if (gw >= BB * NN) return;

    const float* lg = logits + (size_t)gw * CC;
    float v = -FLT_MAX;
    int   vi = 0;
    #pragma unroll
    for (int k = lane; k < CC; k += 32) {
        float x = lg[k];
        if (x > v) { v = x; vi = k; }          // strict > keeps lowest k in-thread
    }
    // warp argmax reduction, tie -> lowest index (matches jnp.argmax)
    #pragma unroll
    for (int off = 16; off; off >>= 1) {
        float v2 = __shfl_down_sync(0xFFFFFFFFu, v, off);
        int   i2 = __shfl_down_sync(0xFFFFFFFFu, vi, off);
        if (v2 > v || (v2 == v && i2 < vi)) { v = v2; vi = i2; }
    }

    if (lane == 0) {
        float ob = objn[gw];
        const float* bx = boxes + (size_t)gw * 4;
        float cx = bx[0], cy = bx[1], w = bx[2], h = bx[3];
        float4 xy;
        xy.x = cx - w * 0.5f;
        xy.y = cy - h * 0.5f;
        xy.z = cx + w * 0.5f;
        xy.w = cy + h * 0.5f;
        bool valid = ob > 0.5f;

        g_key [gw] = valid ? ob : -1.0f;
        g_xyxy[gw] = xy;
        g_obj [gw] = ob;
        g_conf[gw] = v;
        g_cls [gw] = vi;

        int b = gw / NN;
        float* row = out + (size_t)gw * 8;
        ((float4*)row)[0] = make_float4((float)b, 0.f, 0.f, 0.f);
        ((float4*)row)[1] = make_float4(0.f, 0.f, 0.f, 0.f);
    }
}

// ---------------- kernel 2: per-batch stable descending bitonic sort ------
__global__ __launch_bounds__(1024) void sort_kernel()
{
    __shared__ unsigned long long s[NN];
    int b = blockIdx.x;
    int t = threadIdx.x;

    // composite key: orderable(float) in high 32, (0xFFFFFFFF - idx) in low 32
    // -> descending sort on the u64 is stable-descending on the float key.
    for (int i = t; i < NN; i += 1024) {
        unsigned u = __float_as_uint(g_key[b * NN + i]);
        u = (u & 0x80000000u) ? ~u : (u | 0x80000000u);
        s[i] = ((unsigned long long)u << 32) | (unsigned)(0xFFFFFFFFu - (unsigned)i);
    }
    __syncthreads();

    for (int k = 2; k <= NN; k <<= 1) {
        for (int j = k >> 1; j > 0; j >>= 1) {
            #pragma unroll
            for (int r = 0; r < 2; r++) {
                int idx = t + r * 1024;
                int ixj = idx ^ j;
                if (ixj > idx) {
                    unsigned long long a = s[idx], c = s[ixj];
                    bool descSeg = ((idx & k) == 0);
                    bool doSwap  = descSeg ? (a < c) : (a > c);
                    if (doSwap) { s[idx] = c; s[ixj] = a; }
                }
            }
            __syncthreads();
        }
    }

    // gather sorted arrays + detect valid-count boundary
    for (int p = t; p < NN; p += 1024) {
        unsigned long long v = s[p];
        int n = (int)(0xFFFFFFFFu - (unsigned)(v & 0xFFFFFFFFu));
        int src = b * NN + n;
        int dst = b * NN + p;
        g_xyxy_s[dst] = g_xyxy[src];
        g_obj_s [dst] = g_obj [src];
        g_conf_s[dst] = g_conf[src];
        g_cls_s [dst] = (unsigned char)g_cls[src];

        unsigned hu = (unsigned)(v >> 32);
        bool valid_p = hu > 0x80000000u;           // key > 0
        if (p == 0 && !valid_p) g_M[b] = 0;
        if (valid_p) {
            bool nextInvalid = (p == NN - 1) ||
                               ((unsigned)(s[p + 1] >> 32) <= 0x80000000u);
            if (nextInvalid) g_M[b] = p + 1;
        }
    }
}

// ---------------- kernel 3: per-(batch,class) greedy NMS + output --------
#define NMS_WARPS 4
__global__ __launch_bounds__(NMS_WARPS * 32) void nms_kernel(float* __restrict__ out)
{
    __shared__ unsigned short list_s [NMS_WARPS][NN];
    __shared__ unsigned char  alive_s[NMS_WARPS][NN];

    int warp = threadIdx.x >> 5;
    int lane = threadIdx.x & 31;
    int w = blockIdx.x * NMS_WARPS + warp;
    if (w >= BB * CC) return;
    int b = w / CC;
    int c = w % CC;

    int M = g_M[b];
    const unsigned char* cls = g_cls_s + b * NN;
    unsigned short* list  = list_s [warp];
    unsigned char*  alive = alive_s[warp];

    // ordered ballot-compaction of class members within the valid prefix
    int K = 0;
    for (int base = 0; base < M; base += 32) {
        int p = base + lane;
        bool match = (p < M) && (cls[p] == (unsigned char)c);
        unsigned mask = __ballot_sync(0xFFFFFFFFu, match);
        if (match)
            list[K + __popc(mask & ((1u << lane) - 1u))] = (unsigned short)p;
        K += __popc(mask);
    }
    for (int k2 = lane; k2 < K; k2 += 32) alive[k2] = 1;
    __syncwarp();

    const float4* boxes = g_xyxy_s + b * NN;

    for (int i = 0; i < K - 1; i++) {
        if (alive[i]) {
            float4 bi = boxes[list[i]];
            float areaI = (bi.z - bi.x + 1.0f) * (bi.w - bi.y + 1.0f);
            for (int j = i + 1 + lane; j < K; j += 32) {
                if (alive[j]) {
                    float4 bj = boxes[list[j]];
                    float x1 = fmaxf(bi.x, bj.x);
                    float y1 = fmaxf(bi.y, bj.y);
                    float x2 = fminf(bi.z, bj.z);
                    float y2 = fminf(bi.w, bj.w);
                    float iw = fmaxf(x2 - x1 + 1.0f, 0.0f);
                    float ih = fmaxf(y2 - y1 + 1.0f, 0.0f);
                    float inter = iw * ih;
                    float areaJ = (bj.z - bj.x + 1.0f) * (bj.w - bj.y + 1.0f);
                    float iou = inter / (areaI + areaJ - inter);
                    if (iou >= 0.5f) alive[j] = 0;
                }
            }
        }
        __syncwarp();
    }

    // write kept detections
    for (int k2 = lane; k2 < K; k2 += 32) {
        if (alive[k2]) {
            int p = list[k2];
            float4 bx = boxes[p];
            float* row = out + ((size_t)b * NN + p) * 8;
            row[1] = bx.x;
            row[2] = bx.y;
            row[3] = bx.z;
            row[4] = bx.w;
            row[5] = g_obj_s [b * NN + p];
            row[6] = g_conf_s[b * NN + p];
            row[7] = (float)c;
        }
    }
}

// ---------------- launch ---------------------------------------------------
extern "C" void kernel_launch(void* const* d_in, const int* in_sizes, int n_in,
                              void* d_out, int out_size)
{
    const float* boxes  = nullptr;
    const float* objn   = nullptr;
    const float* logits = nullptr;
    for (int i = 0; i < n_in; i++) {
        if      (in_sizes[i] == BB * NN * 4)  boxes  = (const float*)d_in[i];
        else if (in_sizes[i] == BB * NN)      objn   = (const float*)d_in[i];
        else if (in_sizes[i] == BB * NN * CC) logits = (const float*)d_in[i];
    }
    float* out = (float*)d_out;

    int warps  = BB * NN;                       // one warp per element
    int threads = 256;
    int blocks  = (warps * 32 + threads - 1) / threads;
    prep_kernel<<<blocks, threads>>>(boxes, objn, logits, out);

    sort_kernel<<<BB, 1024>>>();

    nms_kernel<<<(BB * CC + NMS_WARPS - 1) / NMS_WARPS, NMS_WARPS * 32>>>(out);
}